// round 5
// baseline (speedup 1.0000x reference)
#include <cuda_runtime.h>
#include <cstdint>

#define N_NODES 100000
#define IN_DIM  512
#define HIDDEN  16
#define OUT_DIM 64

__device__ float g_deg [N_NODES];
__device__ float g_dinv[N_NODES];
__device__ float g_hs1 [N_NODES * HIDDEN];
__device__ float g_acc1[N_NODES * HIDDEN];
__device__ float g_zs  [N_NODES * HIDDEN];
__device__ float g_acc2[N_NODES * HIDDEN];

// ---------------------------------------------------------------------------
__global__ void k_zero() {
    int stride = gridDim.x * blockDim.x;
    int i = blockIdx.x * blockDim.x + threadIdx.x;
    for (int j = i; j < N_NODES * HIDDEN; j += stride) {
        g_acc1[j] = 0.f;
        g_acc2[j] = 0.f;
    }
    for (int j = i; j < N_NODES; j += stride) g_deg[j] = 0.f;
}

__global__ void k_degree(const int* __restrict__ dst, int E) {
    int i = blockIdx.x * blockDim.x + threadIdx.x;
    int e0 = i << 2;
    if (e0 + 3 < E) {
        int4 d = *reinterpret_cast<const int4*>(dst + e0);
        atomicAdd(&g_deg[d.x], 1.0f);
        atomicAdd(&g_deg[d.y], 1.0f);
        atomicAdd(&g_deg[d.z], 1.0f);
        atomicAdd(&g_deg[d.w], 1.0f);
    } else {
        for (int e = e0; e < E; e++) atomicAdd(&g_deg[dst[e]], 1.0f);
    }
}

__global__ void k_dinv() {
    int i = blockIdx.x * blockDim.x + threadIdx.x;
    if (i < N_NODES) g_dinv[i] = rsqrtf(g_deg[i] + 1.0f);   // +1 = self-loop
}

// ---------------------------------------------------------------------------
// GEMM1: hs1[n][f] = (sum_k x[n][k] * W1[k][f]) * dinv[n]
// 256 threads, 128 rows/block (grid=782 -> 5+ blocks/SM).
// Thread = 2 rows (stride 64) x 4 features. Register-prefetch pipeline:
// next chunk LDG'd into regs during compute, STS'd at chunk top.
#define G1_ROWS 128
#define G1_KC   32
#define XS_STR  36                       // floats per row (pad 4, conflict-free)
#define N_CHUNK (IN_DIM / G1_KC)         // 16

__global__ __launch_bounds__(256) void k_gemm1(const float* __restrict__ x,
                                               const float* __restrict__ W1) {
    __shared__ float xs[G1_ROWS * XS_STR];   // 18432 B

    int tid = threadIdx.x;
    int fg4 = tid & 3;                   // feature float4 index 0..3
    int rg  = tid >> 2;                  // row group 0..63
    int row0 = blockIdx.x * G1_ROWS;

    const float4* xg = reinterpret_cast<const float4*>(x);
    const float4* W4 = reinterpret_cast<const float4*>(W1);

    // Staging map: 128 rows x 8 float4 = 1024 float4, 4 per thread
    int s_rr[4], s_cc[4];
    const float4* s_g[4];
    #pragma unroll
    for (int l = 0; l < 4; l++) {
        int idx = tid + l * 256;         // 0..1023
        s_rr[l] = idx >> 3;              // 0..127
        s_cc[l] = idx & 7;               // float4 col within chunk
        int grow = row0 + s_rr[l];
        if (grow >= N_NODES) grow = N_NODES - 1;
        s_g[l] = &xg[(size_t)grow * (IN_DIM / 4) + s_cc[l]];
    }

    float acc[2][4];
    #pragma unroll
    for (int i = 0; i < 2; i++)
        #pragma unroll
        for (int j = 0; j < 4; j++) acc[i][j] = 0.f;

    // Prefetch chunk 0 into registers
    float4 pf[4];
    #pragma unroll
    for (int l = 0; l < 4; l++) pf[l] = __ldg(s_g[l]);

    for (int c = 0; c < N_CHUNK; c++) {
        __syncthreads();                 // smem free (prev compute done)
        #pragma unroll
        for (int l = 0; l < 4; l++)
            *reinterpret_cast<float4*>(&xs[s_rr[l] * XS_STR + s_cc[l] * 4]) = pf[l];
        __syncthreads();

        if (c + 1 < N_CHUNK) {           // prefetch next chunk during compute
            #pragma unroll
            for (int l = 0; l < 4; l++)
                pf[l] = __ldg(s_g[l] + (c + 1) * (G1_KC / 4));
        }

        int kc = c * G1_KC;
        #pragma unroll
        for (int kk = 0; kk < G1_KC; kk += 4) {
            float4 xv0 = *reinterpret_cast<const float4*>(&xs[rg * XS_STR + kk]);
            float4 xv1 = *reinterpret_cast<const float4*>(&xs[(rg + 64) * XS_STR + kk]);
            #pragma unroll
            for (int j = 0; j < 4; j++) {
                float4 w = __ldg(&W4[(kc + kk + j) * 4 + fg4]);
                float x0 = reinterpret_cast<const float*>(&xv0)[j];
                float x1 = reinterpret_cast<const float*>(&xv1)[j];
                acc[0][0] = fmaf(x0, w.x, acc[0][0]);
                acc[0][1] = fmaf(x0, w.y, acc[0][1]);
                acc[0][2] = fmaf(x0, w.z, acc[0][2]);
                acc[0][3] = fmaf(x0, w.w, acc[0][3]);
                acc[1][0] = fmaf(x1, w.x, acc[1][0]);
                acc[1][1] = fmaf(x1, w.y, acc[1][1]);
                acc[1][2] = fmaf(x1, w.z, acc[1][2]);
                acc[1][3] = fmaf(x1, w.w, acc[1][3]);
            }
        }
    }

    #pragma unroll
    for (int i = 0; i < 2; i++) {
        int r = row0 + rg + i * 64;
        if (r < N_NODES) {
            float dv = g_dinv[r];
            float4 o = make_float4(acc[i][0] * dv, acc[i][1] * dv,
                                   acc[i][2] * dv, acc[i][3] * dv);
            *reinterpret_cast<float4*>(&g_hs1[r * HIDDEN + (fg4 << 2)]) = o;
        }
    }
}

// ---------------------------------------------------------------------------
// Edge scatter: acc[dst] += table[src] (16 floats).
// Thread-quad handles 8 edges; thread owns quarter q of each:
//   4 idx LDG.128 (broadcast in quad) + 8 independent gathers + 8 REDs.
__device__ __forceinline__ void red_add_v4(float* p, float4 v) {
    asm volatile("red.global.add.v4.f32 [%0], {%1,%2,%3,%4};"
                 :: "l"(p), "f"(v.x), "f"(v.y), "f"(v.z), "f"(v.w) : "memory");
}

__global__ void k_scatter(const int* __restrict__ src, const int* __restrict__ dst,
                          int E, int phase) {
    int t = blockIdx.x * blockDim.x + threadIdx.x;
    int e0 = (t >> 2) << 3;              // 8 edges per quad
    if (e0 >= E) return;
    int q = (t & 3) << 2;
    const float* tab = phase ? g_zs   : g_hs1;
    float*       acc = phase ? g_acc2 : g_acc1;

    if (e0 + 7 < E) {
        int4 sa = *reinterpret_cast<const int4*>(src + e0);
        int4 sb = *reinterpret_cast<const int4*>(src + e0 + 4);
        int4 da = *reinterpret_cast<const int4*>(dst + e0);
        int4 db = *reinterpret_cast<const int4*>(dst + e0 + 4);
        float4 v0 = *reinterpret_cast<const float4*>(tab + sa.x * HIDDEN + q);
        float4 v1 = *reinterpret_cast<const float4*>(tab + sa.y * HIDDEN + q);
        float4 v2 = *reinterpret_cast<const float4*>(tab + sa.z * HIDDEN + q);
        float4 v3 = *reinterpret_cast<const float4*>(tab + sa.w * HIDDEN + q);
        float4 v4 = *reinterpret_cast<const float4*>(tab + sb.x * HIDDEN + q);
        float4 v5 = *reinterpret_cast<const float4*>(tab + sb.y * HIDDEN + q);
        float4 v6 = *reinterpret_cast<const float4*>(tab + sb.z * HIDDEN + q);
        float4 v7 = *reinterpret_cast<const float4*>(tab + sb.w * HIDDEN + q);
        red_add_v4(acc + da.x * HIDDEN + q, v0);
        red_add_v4(acc + da.y * HIDDEN + q, v1);
        red_add_v4(acc + da.z * HIDDEN + q, v2);
        red_add_v4(acc + da.w * HIDDEN + q, v3);
        red_add_v4(acc + db.x * HIDDEN + q, v4);
        red_add_v4(acc + db.y * HIDDEN + q, v5);
        red_add_v4(acc + db.z * HIDDEN + q, v6);
        red_add_v4(acc + db.w * HIDDEN + q, v7);
    } else {
        for (int e = e0; e < E; e++) {
            int s = src[e], d = dst[e];
            float4 v = *reinterpret_cast<const float4*>(tab + s * HIDDEN + q);
            red_add_v4(acc + d * HIDDEN + q, v);
        }
    }
}

// ---------------------------------------------------------------------------
// Layer-1 epilogue: zs = relu(dinv*(acc1 + hs1) + b1) * dinv   (float4)
__global__ void k_mid(const float* __restrict__ b1) {
    int i = blockIdx.x * blockDim.x + threadIdx.x;          // float4 index
    if (i >= N_NODES * HIDDEN / 4) return;
    int node = i >> 2;
    int f4 = (i & 3) << 2;
    float dv = g_dinv[node];
    float4 a = *reinterpret_cast<const float4*>(&g_acc1[i * 4]);
    float4 h = *reinterpret_cast<const float4*>(&g_hs1[i * 4]);
    float4 b = *reinterpret_cast<const float4*>(&b1[f4]);
    float4 z;
    z.x = fmaxf(fmaf(dv, a.x + h.x, b.x), 0.f) * dv;
    z.y = fmaxf(fmaf(dv, a.y + h.y, b.y), 0.f) * dv;
    z.z = fmaxf(fmaf(dv, a.z + h.z, b.z), 0.f) * dv;
    z.w = fmaxf(fmaf(dv, a.w + h.w, b.w), 0.f) * dv;
    *reinterpret_cast<float4*>(&g_zs[i * 4]) = z;
}

// ---------------------------------------------------------------------------
// Final: agg[d] = dinv[d]*(acc2[d] + zs[d]);  out[d] = agg @ W2 + b2
__global__ __launch_bounds__(256) void k_final(const float* __restrict__ W2,
                                               const float* __restrict__ b2,
                                               float* __restrict__ out) {
    __shared__ float W2s[HIDDEN * OUT_DIM];
    __shared__ float aggs[4][HIDDEN];
    int tid = threadIdx.x;
    for (int j = tid; j < HIDDEN * OUT_DIM; j += 256) W2s[j] = W2[j];

    int n = tid >> 6;
    int o = tid & 63;
    int node = blockIdx.x * 4 + n;

    if (o < HIDDEN) {
        float dv = g_dinv[node];
        int idx = node * HIDDEN + o;
        aggs[n][o] = dv * (g_acc2[idx] + g_zs[idx]);
    }
    __syncthreads();

    float acc = b2[o];
    #pragma unroll
    for (int k = 0; k < HIDDEN; k++)
        acc = fmaf(aggs[n][k], W2s[k * OUT_DIM + o], acc);
    out[(size_t)node * OUT_DIM + o] = acc;
}

// ---------------------------------------------------------------------------
extern "C" void kernel_launch(void* const* d_in, const int* in_sizes, int n_in,
                              void* d_out, int out_size) {
    const float* x  = (const float*)d_in[0];
    const float* W1 = (const float*)d_in[1];
    const float* b1 = (const float*)d_in[2];
    const float* W2 = (const float*)d_in[3];
    const float* b2 = (const float*)d_in[4];
    const int*   ei = (const int*)d_in[5];
    float* out = (float*)d_out;

    int E = in_sizes[5] / 2;
    const int* src = ei;
    const int* dst = ei + E;

    k_zero  <<<1024, 256>>>();
    k_degree<<<(E / 4 + 255) / 256, 256>>>(dst, E);
    k_dinv  <<<(N_NODES + 255) / 256, 256>>>();
    k_gemm1 <<<(N_NODES + G1_ROWS - 1) / G1_ROWS, 256>>>(x, W1);
    k_scatter<<<(E / 2 + 255) / 256, 256>>>(src, dst, E, 0);
    k_mid   <<<(N_NODES * HIDDEN / 4 + 255) / 256, 256>>>(b1);
    k_scatter<<<(E / 2 + 255) / 256, 256>>>(src, dst, E, 1);
    k_final <<<N_NODES / 4, 256>>>(W2, b2, out);
}

// round 7
// speedup vs baseline: 1.0820x; 1.0820x over previous
#include <cuda_runtime.h>
#include <cstdint>

#define N_NODES 100000
#define IN_DIM  512
#define HIDDEN  16
#define OUT_DIM 64
#define MAX_E   3200000
#define NB      98            // ceil(100000/1024) scan blocks

__device__ int   g_degi[N_NODES];
__device__ int   g_row [N_NODES];
__device__ int   g_cur [N_NODES];
__device__ int   g_csr [MAX_E];
__device__ int   g_bsum[NB];
__device__ int   g_boff[NB];
__device__ float g_dinv[N_NODES];
__device__ float g_hs1 [N_NODES * HIDDEN];   // (x@W1) * dinv
__device__ float g_zs  [N_NODES * HIDDEN];   // relu(layer1) * dinv

// ---------------------------------------------------------------------------
__global__ void k_zero_deg() {
    int i = blockIdx.x * blockDim.x + threadIdx.x;
    if (i < N_NODES) g_degi[i] = 0;
}

__global__ void k_degree(const int* __restrict__ dst, int E) {
    int e0 = (blockIdx.x * blockDim.x + threadIdx.x) << 2;
    if (e0 + 3 < E) {
        int4 d = *reinterpret_cast<const int4*>(dst + e0);
        atomicAdd(&g_degi[d.x], 1);
        atomicAdd(&g_degi[d.y], 1);
        atomicAdd(&g_degi[d.z], 1);
        atomicAdd(&g_degi[d.w], 1);
    } else {
        for (int e = e0; e < E; e++) atomicAdd(&g_degi[dst[e]], 1);
    }
}

__global__ void k_dinv() {
    int i = blockIdx.x * blockDim.x + threadIdx.x;
    if (i < N_NODES) g_dinv[i] = rsqrtf((float)g_degi[i] + 1.0f);  // +1 self-loop
}

// --- prefix scan (3 kernels): row_start = exclusive_scan(deg) ---------------
__global__ void k_scan1() {                  // per-block sums (1024 nodes/block)
    int t = threadIdx.x;
    int base = blockIdx.x * 1024 + t * 4;
    int s = 0;
    #pragma unroll
    for (int u = 0; u < 4; u++) {
        int n = base + u;
        if (n < N_NODES) s += g_degi[n];
    }
    #pragma unroll
    for (int off = 16; off >= 1; off >>= 1)
        s += __shfl_xor_sync(0xffffffffu, s, off);
    __shared__ int ws[8];
    if ((t & 31) == 0) ws[t >> 5] = s;
    __syncthreads();
    if (t == 0) {
        int r = 0;
        for (int w = 0; w < 8; w++) r += ws[w];
        g_bsum[blockIdx.x] = r;
    }
}

__global__ void k_scan2() {                  // exclusive scan of NB block sums
    __shared__ int sm[NB];
    int t = threadIdx.x;
    if (t < NB) sm[t] = g_bsum[t];
    __syncthreads();
    if (t == 0) {
        int r = 0;
        for (int b = 0; b < NB; b++) { int v = sm[b]; sm[b] = r; r += v; }
    }
    __syncthreads();
    if (t < NB) g_boff[t] = sm[t];
}

__global__ void k_scan3() {                  // write row_start + cursor
    int t = threadIdx.x;
    int lane = t & 31, wid = t >> 5;
    int base = blockIdx.x * 1024 + t * 4;
    int d[4];
    int s = 0;
    #pragma unroll
    for (int u = 0; u < 4; u++) {
        int n = base + u;
        d[u] = (n < N_NODES) ? g_degi[n] : 0;
        s += d[u];
    }
    int ps = s;
    #pragma unroll
    for (int off = 1; off < 32; off <<= 1) {
        int v = __shfl_up_sync(0xffffffffu, ps, off);
        if (lane >= off) ps += v;
    }
    __shared__ int ws[8];
    if (lane == 31) ws[wid] = ps;
    __syncthreads();
    if (t == 0) {
        int r = 0;
        for (int w = 0; w < 8; w++) { int v = ws[w]; ws[w] = r; r += v; }
    }
    __syncthreads();
    int excl = ps - s + ws[wid] + g_boff[blockIdx.x];
    #pragma unroll
    for (int u = 0; u < 4; u++) {
        int n = base + u;
        if (n < N_NODES) { g_row[n] = excl; g_cur[n] = excl; }
        excl += d[u];
    }
}

__global__ void k_fill(const int* __restrict__ src, const int* __restrict__ dst,
                       int E) {
    int e0 = (blockIdx.x * blockDim.x + threadIdx.x) << 2;
    if (e0 + 3 < E) {
        int4 s = *reinterpret_cast<const int4*>(src + e0);
        int4 d = *reinterpret_cast<const int4*>(dst + e0);
        g_csr[atomicAdd(&g_cur[d.x], 1)] = s.x;
        g_csr[atomicAdd(&g_cur[d.y], 1)] = s.y;
        g_csr[atomicAdd(&g_cur[d.z], 1)] = s.z;
        g_csr[atomicAdd(&g_cur[d.w], 1)] = s.w;
    } else {
        for (int e = e0; e < E; e++)
            g_csr[atomicAdd(&g_cur[dst[e]], 1)] = src[e];
    }
}

// ---------------------------------------------------------------------------
// GEMM1 (proven 85us FFMA design): hs1[n][f] = (sum_k x[n][k]*W1[k][f])*dinv[n]
#define G1_ROWS 256
#define G1_KC   32
#define XS_STR  36

__global__ __launch_bounds__(256) void k_gemm1(const float* __restrict__ x,
                                               const float* __restrict__ W1) {
    __shared__ float xs[G1_ROWS * XS_STR];

    int tid = threadIdx.x;
    int fg4 = tid & 3;
    int rg  = tid >> 2;
    int row0 = blockIdx.x * G1_ROWS;

    const float4* xg = reinterpret_cast<const float4*>(x);
    const float4* W4 = reinterpret_cast<const float4*>(W1);

    float acc[4][4];
    #pragma unroll
    for (int i = 0; i < 4; i++)
        #pragma unroll
        for (int j = 0; j < 4; j++) acc[i][j] = 0.f;

    for (int kc = 0; kc < IN_DIM; kc += G1_KC) {
        __syncthreads();
        #pragma unroll
        for (int l = 0; l < 8; l++) {
            int idx = tid + l * 256;
            int rr = idx >> 3;
            int cc = idx & 7;
            int grow = row0 + rr;
            if (grow >= N_NODES) grow = N_NODES - 1;
            float4 v = xg[(size_t)grow * (IN_DIM / 4) + (kc >> 2) + cc];
            *reinterpret_cast<float4*>(&xs[rr * XS_STR + cc * 4]) = v;
        }
        __syncthreads();

        #pragma unroll
        for (int kk = 0; kk < G1_KC; kk += 4) {
            float4 xv[4];
            #pragma unroll
            for (int i = 0; i < 4; i++)
                xv[i] = *reinterpret_cast<const float4*>(
                    &xs[(rg + i * 64) * XS_STR + kk]);
            #pragma unroll
            for (int j = 0; j < 4; j++) {
                float4 w = __ldg(&W4[(kc + kk + j) * 4 + fg4]);
                #pragma unroll
                for (int i = 0; i < 4; i++) {
                    float xj = reinterpret_cast<const float*>(&xv[i])[j];
                    acc[i][0] = fmaf(xj, w.x, acc[i][0]);
                    acc[i][1] = fmaf(xj, w.y, acc[i][1]);
                    acc[i][2] = fmaf(xj, w.z, acc[i][2]);
                    acc[i][3] = fmaf(xj, w.w, acc[i][3]);
                }
            }
        }
    }

    #pragma unroll
    for (int i = 0; i < 4; i++) {
        int r = row0 + rg + i * 64;
        if (r < N_NODES) {
            float dv = g_dinv[r];
            float4 o = make_float4(acc[i][0] * dv, acc[i][1] * dv,
                                   acc[i][2] * dv, acc[i][3] * dv);
            *reinterpret_cast<float4*>(&g_hs1[r * HIDDEN + (fg4 << 2)]) = o;
        }
    }
}

// ---------------------------------------------------------------------------
// Gather layer 1: warp per node. agg = sum_{e in CSR[node]} hs1[src]
//   zs = relu(dinv*(agg + hs1[node]) + b1) * dinv     (k_mid fused)
__device__ __forceinline__ void quad_reduce(float4& a) {
    #pragma unroll
    for (int off = 4; off <= 16; off <<= 1) {
        a.x += __shfl_xor_sync(0xffffffffu, a.x, off);
        a.y += __shfl_xor_sync(0xffffffffu, a.y, off);
        a.z += __shfl_xor_sync(0xffffffffu, a.z, off);
        a.w += __shfl_xor_sync(0xffffffffu, a.w, off);
    }
}

__global__ __launch_bounds__(256) void k_gather1(const float* __restrict__ b1) {
    int lane = threadIdx.x & 31;
    int node = blockIdx.x * 8 + (threadIdx.x >> 5);
    int q = lane & 3, j = lane >> 2;
    int deg = g_degi[node], start = g_row[node];

    float4 acc = make_float4(0.f, 0.f, 0.f, 0.f);
    int i = j;
    for (; i + 8 < deg; i += 16) {
        int s0 = __ldg(&g_csr[start + i]);
        int s1 = __ldg(&g_csr[start + i + 8]);
        float4 v0 = *reinterpret_cast<const float4*>(&g_hs1[s0 * HIDDEN + q * 4]);
        float4 v1 = *reinterpret_cast<const float4*>(&g_hs1[s1 * HIDDEN + q * 4]);
        acc.x += v0.x + v1.x; acc.y += v0.y + v1.y;
        acc.z += v0.z + v1.z; acc.w += v0.w + v1.w;
    }
    if (i < deg) {
        int s0 = __ldg(&g_csr[start + i]);
        float4 v0 = *reinterpret_cast<const float4*>(&g_hs1[s0 * HIDDEN + q * 4]);
        acc.x += v0.x; acc.y += v0.y; acc.z += v0.z; acc.w += v0.w;
    }
    quad_reduce(acc);

    if (lane < 4) {
        float dv = g_dinv[node];
        float4 hv = *reinterpret_cast<const float4*>(&g_hs1[node * HIDDEN + lane * 4]);
        float4 bb = *reinterpret_cast<const float4*>(&b1[lane * 4]);
        float4 z;
        z.x = fmaxf(fmaf(dv, acc.x + hv.x, bb.x), 0.f) * dv;
        z.y = fmaxf(fmaf(dv, acc.y + hv.y, bb.y), 0.f) * dv;
        z.z = fmaxf(fmaf(dv, acc.z + hv.z, bb.z), 0.f) * dv;
        z.w = fmaxf(fmaf(dv, acc.w + hv.w, bb.w), 0.f) * dv;
        *reinterpret_cast<float4*>(&g_zs[node * HIDDEN + lane * 4]) = z;
    }
}

// ---------------------------------------------------------------------------
// Gather layer 2 + final GEMM: pre = dinv*(agg2 + zs[node]); out = pre@W2 + b2
__global__ __launch_bounds__(256) void k_gather2(const float* __restrict__ W2,
                                                 const float* __restrict__ b2,
                                                 float* __restrict__ out) {
    __shared__ float W2s[HIDDEN * OUT_DIM];   // 4 KB
    __shared__ float pre[8][HIDDEN];
    int tid = threadIdx.x;
    for (int k = tid; k < HIDDEN * OUT_DIM; k += 256) W2s[k] = W2[k];
    __syncthreads();

    int lane = tid & 31, wib = tid >> 5;
    int node = blockIdx.x * 8 + wib;
    int q = lane & 3, j = lane >> 2;
    int deg = g_degi[node], start = g_row[node];

    float4 acc = make_float4(0.f, 0.f, 0.f, 0.f);
    int i = j;
    for (; i + 8 < deg; i += 16) {
        int s0 = __ldg(&g_csr[start + i]);
        int s1 = __ldg(&g_csr[start + i + 8]);
        float4 v0 = *reinterpret_cast<const float4*>(&g_zs[s0 * HIDDEN + q * 4]);
        float4 v1 = *reinterpret_cast<const float4*>(&g_zs[s1 * HIDDEN + q * 4]);
        acc.x += v0.x + v1.x; acc.y += v0.y + v1.y;
        acc.z += v0.z + v1.z; acc.w += v0.w + v1.w;
    }
    if (i < deg) {
        int s0 = __ldg(&g_csr[start + i]);
        float4 v0 = *reinterpret_cast<const float4*>(&g_zs[s0 * HIDDEN + q * 4]);
        acc.x += v0.x; acc.y += v0.y; acc.z += v0.z; acc.w += v0.w;
    }
    quad_reduce(acc);

    if (lane < 4) {
        float dv = g_dinv[node];
        float4 zv = *reinterpret_cast<const float4*>(&g_zs[node * HIDDEN + lane * 4]);
        float4 p;
        p.x = dv * (acc.x + zv.x);
        p.y = dv * (acc.y + zv.y);
        p.z = dv * (acc.z + zv.z);
        p.w = dv * (acc.w + zv.w);
        *reinterpret_cast<float4*>(&pre[wib][lane * 4]) = p;
    }
    __syncwarp();

    float pv[HIDDEN];
    #pragma unroll
    for (int u = 0; u < 4; u++) {
        float4 v = *reinterpret_cast<const float4*>(&pre[wib][u * 4]);
        pv[u * 4 + 0] = v.x; pv[u * 4 + 1] = v.y;
        pv[u * 4 + 2] = v.z; pv[u * 4 + 3] = v.w;
    }
    int o = lane;
    float r0 = __ldg(&b2[o]);
    float r1 = __ldg(&b2[o + 32]);
    #pragma unroll
    for (int k = 0; k < HIDDEN; k++) {
        r0 = fmaf(pv[k], W2s[k * OUT_DIM + o], r0);
        r1 = fmaf(pv[k], W2s[k * OUT_DIM + o + 32], r1);
    }
    out[(size_t)node * OUT_DIM + o] = r0;
    out[(size_t)node * OUT_DIM + o + 32] = r1;
}

// ---------------------------------------------------------------------------
extern "C" void kernel_launch(void* const* d_in, const int* in_sizes, int n_in,
                              void* d_out, int out_size) {
    const float* x  = (const float*)d_in[0];
    const float* W1 = (const float*)d_in[1];
    const float* b1 = (const float*)d_in[2];
    const float* W2 = (const float*)d_in[3];
    const float* b2 = (const float*)d_in[4];
    const int*   ei = (const int*)d_in[5];
    float* out = (float*)d_out;

    int E = in_sizes[5] / 2;
    const int* src = ei;
    const int* dst = ei + E;

    k_zero_deg<<<(N_NODES + 255) / 256, 256>>>();
    k_degree  <<<(E / 4 + 255) / 256, 256>>>(dst, E);
    k_dinv    <<<(N_NODES + 255) / 256, 256>>>();
    k_scan1   <<<NB, 256>>>();
    k_scan2   <<<1, 128>>>();
    k_scan3   <<<NB, 256>>>();
    k_fill    <<<(E / 4 + 255) / 256, 256>>>(src, dst, E);
    k_gemm1   <<<(N_NODES + G1_ROWS - 1) / G1_ROWS, 256>>>(x, W1);
    k_gather1 <<<N_NODES / 8, 256>>>(b1);
    k_gather2 <<<N_NODES / 8, 256>>>(W2, b2, out);
}

// round 9
// speedup vs baseline: 1.2516x; 1.1568x over previous
#include <cuda_runtime.h>
#include <cstdint>

#define N_NODES 100000
#define IN_DIM  512
#define HIDDEN  16
#define OUT_DIM 64

__device__ float g_deg [N_NODES];
__device__ float g_dinv[N_NODES];
__device__ float g_hs1 [N_NODES * HIDDEN];
__device__ float g_acc1[N_NODES * HIDDEN];
__device__ float g_zs  [N_NODES * HIDDEN];
__device__ float g_acc2[N_NODES * HIDDEN];

// ---------------------------------------------------------------------------
__global__ void k_zero() {
    int stride = gridDim.x * blockDim.x;
    int i = blockIdx.x * blockDim.x + threadIdx.x;
    for (int j = i; j < N_NODES * HIDDEN; j += stride) {
        g_acc1[j] = 0.f;
        g_acc2[j] = 0.f;
    }
    for (int j = i; j < N_NODES; j += stride) g_deg[j] = 0.f;
}

__global__ void k_degree(const int* __restrict__ dst, int E) {
    int e0 = (blockIdx.x * blockDim.x + threadIdx.x) << 2;
    if (e0 + 3 < E) {
        int4 d = *reinterpret_cast<const int4*>(dst + e0);
        atomicAdd(&g_deg[d.x], 1.0f);
        atomicAdd(&g_deg[d.y], 1.0f);
        atomicAdd(&g_deg[d.z], 1.0f);
        atomicAdd(&g_deg[d.w], 1.0f);
    } else {
        for (int e = e0; e < E; e++) atomicAdd(&g_deg[dst[e]], 1.0f);
    }
}

__global__ void k_dinv() {
    int i = blockIdx.x * blockDim.x + threadIdx.x;
    if (i < N_NODES) g_dinv[i] = rsqrtf(g_deg[i] + 1.0f);   // +1 = self-loop
}

// ---------------------------------------------------------------------------
// GEMM1 via 3x-tf32 mma.sync: hs1[n][f] = (sum_k x[n][k]*W1[k][f]) * dinv[n]
// 256 thr = 8 warps x 16 rows. A = x (row-major), B = W1 chunk (k x 16).
// Split: a = ah + al, ah = trunc-to-tf32(a); D += Ah*Bh + Al*Bh + Ah*Bl.
#define G1_ROWS 128
#define G1_KC   32
#define XS_STR  36           // conflict-free for A-frag LDS (4*gid+tq distinct)
#define W_STR   24           // conflict-free for B-frag LDS

#define TF32_HI(u) ((u) & 0xFFFFE000u)

__device__ __forceinline__ void mma_tf32(float c[4],
                                         uint32_t a0, uint32_t a1,
                                         uint32_t a2, uint32_t a3,
                                         uint32_t b0, uint32_t b1) {
    asm("mma.sync.aligned.m16n8k8.row.col.f32.tf32.tf32.f32 "
        "{%0,%1,%2,%3}, {%4,%5,%6,%7}, {%8,%9}, {%0,%1,%2,%3};"
        : "+f"(c[0]), "+f"(c[1]), "+f"(c[2]), "+f"(c[3])
        : "r"(a0), "r"(a1), "r"(a2), "r"(a3), "r"(b0), "r"(b1));
}

__global__ __launch_bounds__(256) void k_gemm1(const float* __restrict__ x,
                                               const float* __restrict__ W1) {
    __shared__ float xs[G1_ROWS * XS_STR];   // 18432 B
    __shared__ float wh[G1_KC * W_STR];      // 3072 B (tf32-hi of W chunk)
    __shared__ float wl[G1_KC * W_STR];      // 3072 B (residual)

    int tid  = threadIdx.x;
    int warp = tid >> 5, lane = tid & 31;
    int gid  = lane >> 2, tq = lane & 3;     // fragment coords
    int row0 = blockIdx.x * G1_ROWS;

    const float4* xg = reinterpret_cast<const float4*>(x);

    float c[2][4] = {{0.f, 0.f, 0.f, 0.f}, {0.f, 0.f, 0.f, 0.f}};

    for (int kc = 0; kc < IN_DIM; kc += G1_KC) {
        __syncthreads();
        // stage x: 128 rows x 32 k = 1024 float4, 4 per thread, coalesced
        #pragma unroll
        for (int l = 0; l < 4; l++) {
            int idx = tid + l * 256;
            int rr = idx >> 3, cc = idx & 7;
            int grow = row0 + rr;
            if (grow >= N_NODES) grow = N_NODES - 1;
            float4 v = xg[(size_t)grow * (IN_DIM / 4) + (kc >> 2) + cc];
            *reinterpret_cast<float4*>(&xs[rr * XS_STR + cc * 4]) = v;
        }
        // stage W chunk hi/lo: 32 k x 16 n = 512 vals, 2 per thread
        #pragma unroll
        for (int l = 0; l < 2; l++) {
            int idx = tid + l * 256;
            int k = idx >> 4, n = idx & 15;
            float v = __ldg(&W1[(kc + k) * HIDDEN + n]);
            float vh = __uint_as_float(TF32_HI(__float_as_uint(v)));
            wh[k * W_STR + n] = vh;
            wl[k * W_STR + n] = v - vh;      // low bits truncated by HW = fine
        }
        __syncthreads();

        #pragma unroll
        for (int kt = 0; kt < G1_KC / 8; kt++) {
            // A fragment (rows warp*16+gid, +8; cols kt*8+tq, +4)
            const float* ap = &xs[(warp * 16 + gid) * XS_STR + kt * 8 + tq];
            float a0f = ap[0];
            float a2f = ap[4];
            float a1f = ap[8 * XS_STR];
            float a3f = ap[8 * XS_STR + 4];
            uint32_t ah0 = TF32_HI(__float_as_uint(a0f));
            uint32_t ah1 = TF32_HI(__float_as_uint(a1f));
            uint32_t ah2 = TF32_HI(__float_as_uint(a2f));
            uint32_t ah3 = TF32_HI(__float_as_uint(a3f));
            uint32_t al0 = __float_as_uint(a0f - __uint_as_float(ah0));
            uint32_t al1 = __float_as_uint(a1f - __uint_as_float(ah1));
            uint32_t al2 = __float_as_uint(a2f - __uint_as_float(ah2));
            uint32_t al3 = __float_as_uint(a3f - __uint_as_float(ah3));

            #pragma unroll
            for (int nt = 0; nt < 2; nt++) {
                // B fragment: k = kt*8+tq (+4), n = nt*8+gid
                int bk = (kt * 8 + tq) * W_STR + nt * 8 + gid;
                uint32_t bh0 = __float_as_uint(wh[bk]);
                uint32_t bh1 = __float_as_uint(wh[bk + 4 * W_STR]);
                uint32_t bl0 = __float_as_uint(wl[bk]);
                uint32_t bl1 = __float_as_uint(wl[bk + 4 * W_STR]);
                mma_tf32(c[nt], ah0, ah1, ah2, ah3, bh0, bh1);
                mma_tf32(c[nt], al0, al1, al2, al3, bh0, bh1);
                mma_tf32(c[nt], ah0, ah1, ah2, ah3, bl0, bl1);
            }
        }
    }

    // epilogue: D rows gid/gid+8, cols nt*8 + 2tq/2tq+1
    int r0 = row0 + warp * 16 + gid;
    int r1 = r0 + 8;
    float dv0 = (r0 < N_NODES) ? g_dinv[r0] : 0.f;
    float dv1 = (r1 < N_NODES) ? g_dinv[r1] : 0.f;
    #pragma unroll
    for (int nt = 0; nt < 2; nt++) {
        int f = nt * 8 + tq * 2;
        if (r0 < N_NODES) {
            float2 v = make_float2(c[nt][0] * dv0, c[nt][1] * dv0);
            *reinterpret_cast<float2*>(&g_hs1[r0 * HIDDEN + f]) = v;
        }
        if (r1 < N_NODES) {
            float2 v = make_float2(c[nt][2] * dv1, c[nt][3] * dv1);
            *reinterpret_cast<float2*>(&g_hs1[r1 * HIDDEN + f]) = v;
        }
    }
}

// ---------------------------------------------------------------------------
// Edge scatter: acc[dst] += table[src] (16 floats). Quad handles 8 edges.
__device__ __forceinline__ void red_add_v4(float* p, float4 v) {
    asm volatile("red.global.add.v4.f32 [%0], {%1,%2,%3,%4};"
                 :: "l"(p), "f"(v.x), "f"(v.y), "f"(v.z), "f"(v.w) : "memory");
}

__global__ void k_scatter(const int* __restrict__ src, const int* __restrict__ dst,
                          int E, int phase) {
    int t = blockIdx.x * blockDim.x + threadIdx.x;
    int e0 = (t >> 2) << 3;
    if (e0 >= E) return;
    int q = (t & 3) << 2;
    const float* tab = phase ? g_zs   : g_hs1;
    float*       acc = phase ? g_acc2 : g_acc1;

    if (e0 + 7 < E) {
        int4 sa = *reinterpret_cast<const int4*>(src + e0);
        int4 sb = *reinterpret_cast<const int4*>(src + e0 + 4);
        int4 da = *reinterpret_cast<const int4*>(dst + e0);
        int4 db = *reinterpret_cast<const int4*>(dst + e0 + 4);
        float4 v0 = *reinterpret_cast<const float4*>(tab + sa.x * HIDDEN + q);
        float4 v1 = *reinterpret_cast<const float4*>(tab + sa.y * HIDDEN + q);
        float4 v2 = *reinterpret_cast<const float4*>(tab + sa.z * HIDDEN + q);
        float4 v3 = *reinterpret_cast<const float4*>(tab + sa.w * HIDDEN + q);
        float4 v4 = *reinterpret_cast<const float4*>(tab + sb.x * HIDDEN + q);
        float4 v5 = *reinterpret_cast<const float4*>(tab + sb.y * HIDDEN + q);
        float4 v6 = *reinterpret_cast<const float4*>(tab + sb.z * HIDDEN + q);
        float4 v7 = *reinterpret_cast<const float4*>(tab + sb.w * HIDDEN + q);
        red_add_v4(acc + da.x * HIDDEN + q, v0);
        red_add_v4(acc + da.y * HIDDEN + q, v1);
        red_add_v4(acc + da.z * HIDDEN + q, v2);
        red_add_v4(acc + da.w * HIDDEN + q, v3);
        red_add_v4(acc + db.x * HIDDEN + q, v4);
        red_add_v4(acc + db.y * HIDDEN + q, v5);
        red_add_v4(acc + db.z * HIDDEN + q, v6);
        red_add_v4(acc + db.w * HIDDEN + q, v7);
    } else {
        for (int e = e0; e < E; e++) {
            int s = src[e], d = dst[e];
            float4 v = *reinterpret_cast<const float4*>(tab + s * HIDDEN + q);
            red_add_v4(acc + d * HIDDEN + q, v);
        }
    }
}

// ---------------------------------------------------------------------------
__global__ void k_mid(const float* __restrict__ b1) {
    int i = blockIdx.x * blockDim.x + threadIdx.x;
    if (i >= N_NODES * HIDDEN / 4) return;
    int node = i >> 2;
    int f4 = (i & 3) << 2;
    float dv = g_dinv[node];
    float4 a = *reinterpret_cast<const float4*>(&g_acc1[i * 4]);
    float4 h = *reinterpret_cast<const float4*>(&g_hs1[i * 4]);
    float4 b = *reinterpret_cast<const float4*>(&b1[f4]);
    float4 z;
    z.x = fmaxf(fmaf(dv, a.x + h.x, b.x), 0.f) * dv;
    z.y = fmaxf(fmaf(dv, a.y + h.y, b.y), 0.f) * dv;
    z.z = fmaxf(fmaf(dv, a.z + h.z, b.z), 0.f) * dv;
    z.w = fmaxf(fmaf(dv, a.w + h.w, b.w), 0.f) * dv;
    *reinterpret_cast<float4*>(&g_zs[i * 4]) = z;
}

// ---------------------------------------------------------------------------
__global__ __launch_bounds__(256) void k_final(const float* __restrict__ W2,
                                               const float* __restrict__ b2,
                                               float* __restrict__ out) {
    __shared__ float W2s[HIDDEN * OUT_DIM];
    __shared__ float aggs[4][HIDDEN];
    int tid = threadIdx.x;
    for (int j = tid; j < HIDDEN * OUT_DIM; j += 256) W2s[j] = W2[j];

    int n = tid >> 6;
    int o = tid & 63;
    int node = blockIdx.x * 4 + n;

    if (o < HIDDEN) {
        float dv = g_dinv[node];
        int idx = node * HIDDEN + o;
        aggs[n][o] = dv * (g_acc2[idx] + g_zs[idx]);
    }
    __syncthreads();

    float acc = b2[o];
    #pragma unroll
    for (int k = 0; k < HIDDEN; k++)
        acc = fmaf(aggs[n][k], W2s[k * OUT_DIM + o], acc);
    out[(size_t)node * OUT_DIM + o] = acc;
}

// ---------------------------------------------------------------------------
extern "C" void kernel_launch(void* const* d_in, const int* in_sizes, int n_in,
                              void* d_out, int out_size) {
    const float* x  = (const float*)d_in[0];
    const float* W1 = (const float*)d_in[1];
    const float* b1 = (const float*)d_in[2];
    const float* W2 = (const float*)d_in[3];
    const float* b2 = (const float*)d_in[4];
    const int*   ei = (const int*)d_in[5];
    float* out = (float*)d_out;

    int E = in_sizes[5] / 2;
    const int* src = ei;
    const int* dst = ei + E;

    k_zero  <<<1024, 256>>>();
    k_degree<<<(E / 4 + 255) / 256, 256>>>(dst, E);
    k_dinv  <<<(N_NODES + 255) / 256, 256>>>();
    k_gemm1 <<<(N_NODES + G1_ROWS - 1) / G1_ROWS, 256>>>(x, W1);
    k_scatter<<<(E / 2 + 255) / 256, 256>>>(src, dst, E, 0);
    k_mid   <<<(N_NODES * HIDDEN / 4 + 255) / 256, 256>>>(b1);
    k_scatter<<<(E / 2 + 255) / 256, 256>>>(src, dst, E, 1);
    k_final <<<N_NODES / 4, 256>>>(W2, b2, out);
}

// round 11
// speedup vs baseline: 1.2853x; 1.0270x over previous
#include <cuda_runtime.h>
#include <cstdint>

#define N_NODES 100000
#define IN_DIM  512
#define HIDDEN  16
#define OUT_DIM 64

__device__ float g_deg [N_NODES];
__device__ float g_dinv[N_NODES];
__device__ float g_hs1 [N_NODES * HIDDEN];
__device__ float g_acc1[N_NODES * HIDDEN];
__device__ float g_zs  [N_NODES * HIDDEN];
__device__ float g_acc2[N_NODES * HIDDEN];

// ---------------------------------------------------------------------------
__global__ void k_zero() {
    int stride = gridDim.x * blockDim.x;
    int i = blockIdx.x * blockDim.x + threadIdx.x;
    for (int j = i; j < N_NODES * HIDDEN; j += stride) {
        g_acc1[j] = 0.f;
        g_acc2[j] = 0.f;
    }
    for (int j = i; j < N_NODES; j += stride) g_deg[j] = 0.f;
}

__global__ void k_degree(const int* __restrict__ dst, int E) {
    int e0 = (blockIdx.x * blockDim.x + threadIdx.x) << 2;
    if (e0 + 3 < E) {
        int4 d = *reinterpret_cast<const int4*>(dst + e0);
        atomicAdd(&g_deg[d.x], 1.0f);
        atomicAdd(&g_deg[d.y], 1.0f);
        atomicAdd(&g_deg[d.z], 1.0f);
        atomicAdd(&g_deg[d.w], 1.0f);
    } else {
        for (int e = e0; e < E; e++) atomicAdd(&g_deg[dst[e]], 1.0f);
    }
}

__global__ void k_dinv() {
    int i = blockIdx.x * blockDim.x + threadIdx.x;
    if (i < N_NODES) g_dinv[i] = rsqrtf(g_deg[i] + 1.0f);   // +1 = self-loop
}

// ---------------------------------------------------------------------------
// GEMM1 via 3x-tf32 mma.sync + 3-stage cp.async pipeline.
// hs1[n][f] = (sum_k x[n][k]*W1[k][f]) * dinv[n]
// 256 thr = 8 warps x 16 rows; 128 rows/block. W fragments direct __ldg.
#define G1_ROWS 128
#define G1_KC   32
#define XS_STR  36                 // floats/row; 144B = 9*16 -> cp.async-aligned
#define N_CHUNK (IN_DIM / G1_KC)   // 16
#define N_STG   3
#define STG_FLT (G1_ROWS * XS_STR) // 4608 floats = 18432 B per stage

#define TF32_HI(u) ((u) & 0xFFFFE000u)

__device__ __forceinline__ void cp_async16(unsigned int saddr, const void* gptr) {
    asm volatile("cp.async.cg.shared.global [%0], [%1], 16;"
                 :: "r"(saddr), "l"(gptr) : "memory");
}

__device__ __forceinline__ void mma_tf32(float c[4],
                                         uint32_t a0, uint32_t a1,
                                         uint32_t a2, uint32_t a3,
                                         uint32_t b0, uint32_t b1) {
    asm("mma.sync.aligned.m16n8k8.row.col.f32.tf32.tf32.f32 "
        "{%0,%1,%2,%3}, {%4,%5,%6,%7}, {%8,%9}, {%0,%1,%2,%3};"
        : "+f"(c[0]), "+f"(c[1]), "+f"(c[2]), "+f"(c[3])
        : "r"(a0), "r"(a1), "r"(a2), "r"(a3), "r"(b0), "r"(b1));
}

__global__ __launch_bounds__(256) void k_gemm1(const float* __restrict__ x,
                                               const float* __restrict__ W1) {
    extern __shared__ float xs[];            // N_STG * STG_FLT

    int tid  = threadIdx.x;
    int warp = tid >> 5, lane = tid & 31;
    int gid  = lane >> 2, tq = lane & 3;
    int row0 = blockIdx.x * G1_ROWS;

    const float4* xg = reinterpret_cast<const float4*>(x);

    // staging map: 1024 float4 per chunk, 4 per thread
    int s_rr[4], s_cc[4];
    const float4* s_g[4];
    unsigned int s_sm[4];
    #pragma unroll
    for (int l = 0; l < 4; l++) {
        int idx = tid + l * 256;
        s_rr[l] = idx >> 3;
        s_cc[l] = idx & 7;
        int grow = row0 + s_rr[l];
        if (grow >= N_NODES) grow = N_NODES - 1;
        s_g[l]  = &xg[(size_t)grow * (IN_DIM / 4) + s_cc[l]];
        s_sm[l] = (unsigned int)__cvta_generic_to_shared(
                      &xs[s_rr[l] * XS_STR + s_cc[l] * 4]);
    }

    float c[2][4] = {{0.f, 0.f, 0.f, 0.f}, {0.f, 0.f, 0.f, 0.f}};

    // prologue: issue chunks 0 and 1
    #pragma unroll
    for (int p = 0; p < 2; p++) {
        unsigned int soff = (unsigned int)((p % N_STG) * STG_FLT * 4);
        #pragma unroll
        for (int l = 0; l < 4; l++)
            cp_async16(s_sm[l] + soff, s_g[l] + p * (G1_KC / 4));
        asm volatile("cp.async.commit_group;");
    }

    for (int ch = 0; ch < N_CHUNK; ch++) {
        asm volatile("cp.async.wait_group 1;");
        __syncthreads();

        if (ch + 2 < N_CHUNK) {
            unsigned int soff = (unsigned int)(((ch + 2) % N_STG) * STG_FLT * 4);
            #pragma unroll
            for (int l = 0; l < 4; l++)
                cp_async16(s_sm[l] + soff, s_g[l] + (ch + 2) * (G1_KC / 4));
        }
        asm volatile("cp.async.commit_group;");

        const float* xb = &xs[(ch % N_STG) * STG_FLT];
        int kc = ch * G1_KC;

        #pragma unroll
        for (int kt = 0; kt < G1_KC / 8; kt++) {
            const float* ap = &xb[(warp * 16 + gid) * XS_STR + kt * 8 + tq];
            float a0f = ap[0];
            float a2f = ap[4];
            float a1f = ap[8 * XS_STR];
            float a3f = ap[8 * XS_STR + 4];
            uint32_t ah0 = TF32_HI(__float_as_uint(a0f));
            uint32_t ah1 = TF32_HI(__float_as_uint(a1f));
            uint32_t ah2 = TF32_HI(__float_as_uint(a2f));
            uint32_t ah3 = TF32_HI(__float_as_uint(a3f));
            uint32_t al0 = __float_as_uint(a0f - __uint_as_float(ah0));
            uint32_t al1 = __float_as_uint(a1f - __uint_as_float(ah1));
            uint32_t al2 = __float_as_uint(a2f - __uint_as_float(ah2));
            uint32_t al3 = __float_as_uint(a3f - __uint_as_float(ah3));

            int krow = kc + kt * 8 + tq;
            #pragma unroll
            for (int nt = 0; nt < 2; nt++) {
                float b0f = __ldg(&W1[krow * HIDDEN + nt * 8 + gid]);
                float b1f = __ldg(&W1[(krow + 4) * HIDDEN + nt * 8 + gid]);
                uint32_t bh0 = TF32_HI(__float_as_uint(b0f));
                uint32_t bh1 = TF32_HI(__float_as_uint(b1f));
                uint32_t bl0 = __float_as_uint(b0f - __uint_as_float(bh0));
                uint32_t bl1 = __float_as_uint(b1f - __uint_as_float(bh1));
                mma_tf32(c[nt], ah0, ah1, ah2, ah3, bh0, bh1);
                mma_tf32(c[nt], al0, al1, al2, al3, bh0, bh1);
                mma_tf32(c[nt], ah0, ah1, ah2, ah3, bl0, bl1);
            }
        }
    }

    // epilogue: D rows gid/gid+8, cols nt*8 + 2tq/2tq+1
    int r0 = row0 + warp * 16 + gid;
    int r1 = r0 + 8;
    float dv0 = (r0 < N_NODES) ? g_dinv[r0] : 0.f;
    float dv1 = (r1 < N_NODES) ? g_dinv[r1] : 0.f;
    #pragma unroll
    for (int nt = 0; nt < 2; nt++) {
        int f = nt * 8 + tq * 2;
        if (r0 < N_NODES) {
            float2 v = make_float2(c[nt][0] * dv0, c[nt][1] * dv0);
            *reinterpret_cast<float2*>(&g_hs1[r0 * HIDDEN + f]) = v;
        }
        if (r1 < N_NODES) {
            float2 v = make_float2(c[nt][2] * dv1, c[nt][3] * dv1);
            *reinterpret_cast<float2*>(&g_hs1[r1 * HIDDEN + f]) = v;
        }
    }
}

// ---------------------------------------------------------------------------
// Edge scatter: acc[dst] += table[src] (16 floats). Quad handles 8 edges.
__device__ __forceinline__ void red_add_v4(float* p, float4 v) {
    asm volatile("red.global.add.v4.f32 [%0], {%1,%2,%3,%4};"
                 :: "l"(p), "f"(v.x), "f"(v.y), "f"(v.z), "f"(v.w) : "memory");
}

__global__ void k_scatter(const int* __restrict__ src, const int* __restrict__ dst,
                          int E, int phase) {
    int t = blockIdx.x * blockDim.x + threadIdx.x;
    int e0 = (t >> 2) << 3;
    if (e0 >= E) return;
    int q = (t & 3) << 2;
    const float* tab = phase ? g_zs   : g_hs1;
    float*       acc = phase ? g_acc2 : g_acc1;

    if (e0 + 7 < E) {
        int4 sa = *reinterpret_cast<const int4*>(src + e0);
        int4 sb = *reinterpret_cast<const int4*>(src + e0 + 4);
        int4 da = *reinterpret_cast<const int4*>(dst + e0);
        int4 db = *reinterpret_cast<const int4*>(dst + e0 + 4);
        float4 v0 = *reinterpret_cast<const float4*>(tab + sa.x * HIDDEN + q);
        float4 v1 = *reinterpret_cast<const float4*>(tab + sa.y * HIDDEN + q);
        float4 v2 = *reinterpret_cast<const float4*>(tab + sa.z * HIDDEN + q);
        float4 v3 = *reinterpret_cast<const float4*>(tab + sa.w * HIDDEN + q);
        float4 v4 = *reinterpret_cast<const float4*>(tab + sb.x * HIDDEN + q);
        float4 v5 = *reinterpret_cast<const float4*>(tab + sb.y * HIDDEN + q);
        float4 v6 = *reinterpret_cast<const float4*>(tab + sb.z * HIDDEN + q);
        float4 v7 = *reinterpret_cast<const float4*>(tab + sb.w * HIDDEN + q);
        red_add_v4(acc + da.x * HIDDEN + q, v0);
        red_add_v4(acc + da.y * HIDDEN + q, v1);
        red_add_v4(acc + da.z * HIDDEN + q, v2);
        red_add_v4(acc + da.w * HIDDEN + q, v3);
        red_add_v4(acc + db.x * HIDDEN + q, v4);
        red_add_v4(acc + db.y * HIDDEN + q, v5);
        red_add_v4(acc + db.z * HIDDEN + q, v6);
        red_add_v4(acc + db.w * HIDDEN + q, v7);
    } else {
        for (int e = e0; e < E; e++) {
            int s = src[e], d = dst[e];
            float4 v = *reinterpret_cast<const float4*>(tab + s * HIDDEN + q);
            red_add_v4(acc + d * HIDDEN + q, v);
        }
    }
}

// ---------------------------------------------------------------------------
__global__ void k_mid(const float* __restrict__ b1) {
    int i = blockIdx.x * blockDim.x + threadIdx.x;
    if (i >= N_NODES * HIDDEN / 4) return;
    int node = i >> 2;
    int f4 = (i & 3) << 2;
    float dv = g_dinv[node];
    float4 a = *reinterpret_cast<const float4*>(&g_acc1[i * 4]);
    float4 h = *reinterpret_cast<const float4*>(&g_hs1[i * 4]);
    float4 b = *reinterpret_cast<const float4*>(&b1[f4]);
    float4 z;
    z.x = fmaxf(fmaf(dv, a.x + h.x, b.x), 0.f) * dv;
    z.y = fmaxf(fmaf(dv, a.y + h.y, b.y), 0.f) * dv;
    z.z = fmaxf(fmaf(dv, a.z + h.z, b.z), 0.f) * dv;
    z.w = fmaxf(fmaf(dv, a.w + h.w, b.w), 0.f) * dv;
    *reinterpret_cast<float4*>(&g_zs[i * 4]) = z;
}

// ---------------------------------------------------------------------------
__global__ __launch_bounds__(256) void k_final(const float* __restrict__ W2,
                                               const float* __restrict__ b2,
                                               float* __restrict__ out) {
    __shared__ float W2s[HIDDEN * OUT_DIM];
    __shared__ float aggs[4][HIDDEN];
    int tid = threadIdx.x;
    for (int j = tid; j < HIDDEN * OUT_DIM; j += 256) W2s[j] = W2[j];

    int n = tid >> 6;
    int o = tid & 63;
    int node = blockIdx.x * 4 + n;

    if (o < HIDDEN) {
        float dv = g_dinv[node];
        int idx = node * HIDDEN + o;
        aggs[n][o] = dv * (g_acc2[idx] + g_zs[idx]);
    }
    __syncthreads();

    float acc = b2[o];
    #pragma unroll
    for (int k = 0; k < HIDDEN; k++)
        acc = fmaf(aggs[n][k], W2s[k * OUT_DIM + o], acc);
    out[(size_t)node * OUT_DIM + o] = acc;
}

// ---------------------------------------------------------------------------
extern "C" void kernel_launch(void* const* d_in, const int* in_sizes, int n_in,
                              void* d_out, int out_size) {
    const float* x  = (const float*)d_in[0];
    const float* W1 = (const float*)d_in[1];
    const float* b1 = (const float*)d_in[2];
    const float* W2 = (const float*)d_in[3];
    const float* b2 = (const float*)d_in[4];
    const int*   ei = (const int*)d_in[5];
    float* out = (float*)d_out;

    int E = in_sizes[5] / 2;
    const int* src = ei;
    const int* dst = ei + E;

    const int smem_bytes = N_STG * STG_FLT * 4;   // 55296
    cudaFuncSetAttribute(k_gemm1, cudaFuncAttributeMaxDynamicSharedMemorySize,
                         smem_bytes);

    k_zero  <<<1024, 256>>>();
    k_degree<<<(E / 4 + 255) / 256, 256>>>(dst, E);
    k_dinv  <<<(N_NODES + 255) / 256, 256>>>();
    k_gemm1 <<<(N_NODES + G1_ROWS - 1) / G1_ROWS, 256, smem_bytes>>>(x, W1);
    k_scatter<<<(E / 2 + 255) / 256, 256>>>(src, dst, E, 0);
    k_mid   <<<(N_NODES * HIDDEN / 4 + 255) / 256, 256>>>(b1);
    k_scatter<<<(E / 2 + 255) / 256, 256>>>(src, dst, E, 1);
    k_final <<<N_NODES / 4, 256>>>(W2, b2, out);
}